// round 8
// baseline (speedup 1.0000x reference)
#include <cuda_runtime.h>
#include <cuda_bf16.h>
#include <stdint.h>

#define VV  128000
#define HH  2048
#define BBS 32
#define SSQ 1024
#define VT  128
#define KC  32
#define CAP 4096

// ---------------- scratch (no allocations allowed) ----------------
__device__ float g_cand_val[BBS * CAP];
__device__ int   g_cand_idx[BBS * CAP];
__device__ int   g_cand_cnt[BBS];
__device__ float g_row_max[BBS];
__device__ float g_row_sum[BBS];

// ---------------- packed f32x2 FMA ----------------
__device__ __forceinline__ void ffma2(float &ax, float &ay, float ex, float ey, float h) {
    asm("{\n\t"
        ".reg .b64 e2, h2, a2;\n\t"
        "mov.b64 e2, {%2, %3};\n\t"
        "mov.b64 h2, {%4, %4};\n\t"
        "mov.b64 a2, {%0, %1};\n\t"
        "fma.rn.f32x2 a2, e2, h2, a2;\n\t"
        "mov.b64 {%0, %1}, a2;\n\t"
        "}"
        : "+f"(ax), "+f"(ay)
        : "f"(ex), "f"(ey), "f"(h));
}

// ---------------- Threefry-2x32, JAX partitionable mode, key(42) ----------------
// jax >= 0.5: threefry_partitionable defaults True. For flat element index n:
//   (o0, o1) = threefry2x32(key=(0,42), counter=(hi32(n), lo32(n)) = (0, n))
//   bits     = o0 ^ o1
__device__ __forceinline__ void tf_round(uint32_t &x0, uint32_t &x1, int r) {
    x0 += x1;
    x1 = (x1 << r) | (x1 >> (32 - r));
    x1 ^= x0;
}

__device__ float gumbel_for(uint32_t n) {
    uint32_t x0 = 0u;   // hi32 of 64-bit counter (size < 2^32)
    uint32_t x1 = n;    // lo32
    const uint32_t k0 = 0u, k1 = 42u;
    const uint32_t k2 = 0x1BD11BDAu ^ k0 ^ k1;
    x0 += k0; x1 += k1;
    tf_round(x0,x1,13); tf_round(x0,x1,15); tf_round(x0,x1,26); tf_round(x0,x1,6);
    x0 += k1; x1 += k2 + 1u;
    tf_round(x0,x1,17); tf_round(x0,x1,29); tf_round(x0,x1,16); tf_round(x0,x1,24);
    x0 += k2; x1 += k0 + 2u;
    tf_round(x0,x1,13); tf_round(x0,x1,15); tf_round(x0,x1,26); tf_round(x0,x1,6);
    x0 += k0; x1 += k1 + 3u;
    tf_round(x0,x1,17); tf_round(x0,x1,29); tf_round(x0,x1,16); tf_round(x0,x1,24);
    x0 += k1; x1 += k2 + 4u;
    tf_round(x0,x1,13); tf_round(x0,x1,15); tf_round(x0,x1,26); tf_round(x0,x1,6);
    x0 += k2; x1 += k0 + 5u;
    uint32_t bits = x0 ^ x1;
    // uniform(minval=tiny, maxval=1) then gumbel = -log(-log(u))
    float u = __uint_as_float((bits >> 9) | 0x3f800000u) - 1.0f;
    u = u + 1.17549435e-38f;
    u = fmaxf(1.17549435e-38f, u);
    return -logf(-logf(u));
}

// ---------------- K1: gather + GEMM + softcap + temperature ----------------
#define F2(p,c,ex,ey,h) ffma2(acc[p][c][0], acc[p][c][1], ex, ey, h)

__global__ __launch_bounds__(128, 1)
void k1_gemm(const float* __restrict__ emb, const float* __restrict__ hid,
             const int* __restrict__ posp, const float* __restrict__ temps,
             float* __restrict__ outL)
{
    __shared__ __align__(16) float esT[KC * VT];   // 16 KB, swizzled k-major
    __shared__ __align__(16) float hsT[KC * BBS];  //  4 KB, swizzled k-major

    const int t   = threadIdx.x;
    const int w   = t >> 5, l = t & 31;
    const int vg  = t >> 3;          // 0..15 -> rows vg*8..+7
    const int bgq = t & 7;           // -> batches bgq*4..+3
    const int v0  = blockIdx.x * VT;
    const int pos = posp[0];

    float acc[4][4][2];
    #pragma unroll
    for (int p = 0; p < 4; p++)
        #pragma unroll
        for (int c = 0; c < 4; c++) { acc[p][c][0] = 0.f; acc[p][c][1] = 0.f; }

    float tc[4];
    #pragma unroll
    for (int c = 0; c < 4; c++) tc[c] = temps[bgq * 4 + c];

    const int ek = (l & 7) * 4;
    const int hb = t >> 2;
    const int hk = (t & 3) * 8;
    const float* ebase = emb + (size_t)v0 * HH;
    const float* hrow  = hid + ((size_t)hb * SSQ + pos) * HH;

    float4 ev[8], h0v, h1v;
    #pragma unroll
    for (int i = 0; i < 8; i++) {
        int row = w * 32 + i * 4 + (l >> 3);
        ev[i] = *(const float4*)(ebase + (size_t)row * HH + ek);
    }
    h0v = *(const float4*)(hrow + hk);
    h1v = *(const float4*)(hrow + hk + 4);

    for (int kc = 0; kc < HH; kc += KC) {
        __syncthreads();
        #pragma unroll
        for (int i = 0; i < 8; i++) {
            int row = w * 32 + i * 4 + (l >> 3);
            int rq = row >> 2, rl = row & 3;
            const float* pv = (const float*)&ev[i];
            #pragma unroll
            for (int j = 0; j < 4; j++) {
                int k = ek + j;
                esT[(k * 32 + (rq ^ (k >> 2))) * 4 + rl] = pv[j];
            }
        }
        {
            int bq = hb >> 2, bl = hb & 3;
            #pragma unroll
            for (int j = 0; j < 8; j++) {
                int k = hk + j;
                float v = (j < 4) ? ((const float*)&h0v)[j] : ((const float*)&h1v)[j - 4];
                hsT[(k * 8 + (bq ^ (k & 7))) * 4 + bl] = v;
            }
        }
        __syncthreads();
        int kn = kc + KC;
        if (kn < HH) {
            #pragma unroll
            for (int i = 0; i < 8; i++) {
                int row = w * 32 + i * 4 + (l >> 3);
                ev[i] = *(const float4*)(ebase + (size_t)row * HH + kn + ek);
            }
            h0v = *(const float4*)(hrow + kn + hk);
            h1v = *(const float4*)(hrow + kn + hk + 4);
        }
        #pragma unroll 8
        for (int k = 0; k < KC; k++) {
            float4 eA = *(const float4*)(esT + (k * 32 + ((2 * vg)     ^ (k >> 2))) * 4);
            float4 eB = *(const float4*)(esT + (k * 32 + ((2 * vg + 1) ^ (k >> 2))) * 4);
            float4 hv = *(const float4*)(hsT + (k * 8  + (bgq ^ (k & 7))) * 4);
            F2(0,0,eA.x,eA.y,hv.x); F2(1,0,eA.z,eA.w,hv.x); F2(2,0,eB.x,eB.y,hv.x); F2(3,0,eB.z,eB.w,hv.x);
            F2(0,1,eA.x,eA.y,hv.y); F2(1,1,eA.z,eA.w,hv.y); F2(2,1,eB.x,eB.y,hv.y); F2(3,1,eB.z,eB.w,hv.y);
            F2(0,2,eA.x,eA.y,hv.z); F2(1,2,eA.z,eA.w,hv.z); F2(2,2,eB.x,eB.y,hv.z); F2(3,2,eB.z,eB.w,hv.z);
            F2(0,3,eA.x,eA.y,hv.w); F2(1,3,eA.z,eA.w,hv.w); F2(2,3,eB.x,eB.y,hv.w); F2(3,3,eB.z,eB.w,hv.w);
        }
    }

    #pragma unroll
    for (int c = 0; c < 4; c++) {
        int b = bgq * 4 + c;
        float tv = tc[c];
        float4 lo, hi;
        lo.x = tanhf(acc[0][c][0] / 30.0f) * 30.0f / tv;
        lo.y = tanhf(acc[0][c][1] / 30.0f) * 30.0f / tv;
        lo.z = tanhf(acc[1][c][0] / 30.0f) * 30.0f / tv;
        lo.w = tanhf(acc[1][c][1] / 30.0f) * 30.0f / tv;
        hi.x = tanhf(acc[2][c][0] / 30.0f) * 30.0f / tv;
        hi.y = tanhf(acc[2][c][1] / 30.0f) * 30.0f / tv;
        hi.z = tanhf(acc[3][c][0] / 30.0f) * 30.0f / tv;
        hi.w = tanhf(acc[3][c][1] / 30.0f) * 30.0f / tv;
        float* dst = outL + (size_t)b * VV + v0 + vg * 8;
        *(float4*)dst       = lo;
        *(float4*)(dst + 4) = hi;
    }
}

// ---------------- K2: per-row max, sum(exp), candidate collection ----------------
__global__ void k2_stats(const float* __restrict__ outL)
{
    const int b = blockIdx.x, tid = threadIdx.x;
    const int wid = tid >> 5, lane = tid & 31;
    const float* row = outL + (size_t)b * VV;

    __shared__ float sred[32];
    __shared__ float s_max, s_sum;
    __shared__ int   hist[32 * 64];
    __shared__ int   s_bstar;

    float mx = __int_as_float(0xff800000);
    for (int i = tid; i < VV; i += 1024) mx = fmaxf(mx, row[i]);
    for (int o = 16; o; o >>= 1) mx = fmaxf(mx, __shfl_xor_sync(0xffffffffu, mx, o));
    if (lane == 0) sred[wid] = mx;
    __syncthreads();
    if (tid < 32) {
        float m = sred[tid];
        for (int o = 16; o; o >>= 1) m = fmaxf(m, __shfl_xor_sync(0xffffffffu, m, o));
        if (tid == 0) s_max = m;
    }
    for (int i = tid; i < 32 * 64; i += 1024) hist[i] = 0;
    __syncthreads();
    const float mxv = s_max;

    float sum = 0.f;
    for (int i = tid; i < VV; i += 1024) {
        float lv = row[i];
        sum += expf(lv - mxv);
        int bin = (int)((mxv - lv) * 2.0f); bin = bin > 63 ? 63 : bin;
        atomicAdd(&hist[wid * 64 + bin], 1);
    }
    for (int o = 16; o; o >>= 1) sum += __shfl_xor_sync(0xffffffffu, sum, o);
    if (lane == 0) sred[wid] = sum;
    __syncthreads();
    if (tid < 32) {
        float s = sred[tid];
        for (int o = 16; o; o >>= 1) s += __shfl_xor_sync(0xffffffffu, s, o);
        if (tid == 0) s_sum = s;
    }
    __syncthreads();
    if (tid < 64) {
        int c = 0;
        for (int w2 = 0; w2 < 32; w2++) c += hist[w2 * 64 + tid];
        hist[tid] = c;
    }
    __syncthreads();
    if (tid == 0) {
        int cum = 0, bs = 63;
        for (int i2 = 0; i2 < 64; i2++) { cum += hist[i2]; if (cum >= 64) { bs = i2; break; } }
        s_bstar = bs;
        g_cand_cnt[b] = 0;
        g_row_max[b]  = mxv;
        g_row_sum[b]  = s_sum;
    }
    __syncthreads();
    const int bs = s_bstar;

    for (int i = tid; i < VV; i += 1024) {
        float lv = row[i];
        int bin = (int)((mxv - lv) * 2.0f); bin = bin > 63 ? 63 : bin;
        if (bin <= bs) {
            int p = atomicAdd(&g_cand_cnt[b], 1);
            if (p < CAP) { g_cand_val[b * CAP + p] = lv; g_cand_idx[b * CAP + p] = i; }
        }
    }
}

// ---------------- K3: exact rank, top-p/top-k mask, gumbel argmax ----------------
__global__ void k3_sample(const float* __restrict__ tps, const int* __restrict__ tks,
                          float* __restrict__ out)
{
    const int b = blockIdx.x, tid = threadIdx.x;
    __shared__ float sv[CAP];
    __shared__ int   si[CAP];
    __shared__ float tv[64];
    __shared__ int   tix[64];

    int n = g_cand_cnt[b]; if (n > CAP) n = CAP;
    for (int i = tid; i < n; i += 256) { sv[i] = g_cand_val[b * CAP + i]; si[i] = g_cand_idx[b * CAP + i]; }
    __syncthreads();

    // rank by (value desc, index asc) == stable argsort(-probs)
    for (int j = tid; j < n; j += 256) {
        float v = sv[j]; int id = si[j]; int r = 0;
        for (int i = 0; i < n; i++) {
            float vi = sv[i];
            if (vi > v || (vi == v && si[i] < id)) r++;
        }
        if (r < 64) { tv[r] = v; tix[r] = id; }
    }
    __syncthreads();

    if (tid == 0) {
        int m = n < 64 ? n : 64;
        float mx = g_row_max[b], S = g_row_sum[b];
        float tp = tps[b]; int kk = tks[b];
        float cum = 0.f, best = __int_as_float(0xff800000);
        int bid = 0;
        for (int j = 0; j < m; j++) {
            float p = expf(tv[j] - mx) / S;
            cum += p;
            bool keep = !((cum - p) > tp) && (j < kk);
            if (keep) {
                float sc = tv[j] + gumbel_for((uint32_t)(b * VV + tix[j]));
                if (sc > best) { best = sc; bid = tix[j]; }
            }
        }
        out[b] = (float)bid;
    }
}

// ---------------- launch ----------------
extern "C" void kernel_launch(void* const* d_in, const int* in_sizes, int n_in,
                              void* d_out, int out_size)
{
    const float* emb  = (const float*)d_in[0];  // [V, H]
    const float* hid  = (const float*)d_in[1];  // [B, S, H]
    const int*   posp = (const int*)  d_in[2];  // [1]
    const float* tps  = (const float*)d_in[3];  // [B]
    const int*   tks  = (const int*)  d_in[4];  // [B]
    const float* tmps = (const float*)d_in[5];  // [B]
    float* out  = (float*)d_out;                // [B ids][B*V logits]
    float* outL = out + BBS;

    k1_gemm<<<VV / VT, 128>>>(emb, hid, posp, tmps, outL);
    k2_stats<<<BBS, 1024>>>(outL);
    k3_sample<<<BBS, 256>>>(tps, tks, out);
}

// round 11
// speedup vs baseline: 1.5619x; 1.5619x over previous
#include <cuda_runtime.h>
#include <cuda_bf16.h>
#include <stdint.h>

#define VV  128000
#define HH  2048
#define BBS 32
#define SSQ 1024
#define VT  128          // vocab rows per CTA
#define KCH 64           // K columns per chunk
#define NCH (HH / KCH)   // 32 chunks
#define CAP 4096

// ---------------- scratch ----------------
__device__ float g_cand_val[BBS * CAP];
__device__ int   g_cand_idx[BBS * CAP];
__device__ int   g_cand_cnt[BBS];
__device__ float g_row_max[BBS];
__device__ float g_row_sum[BBS];
__device__ unsigned int g_max_enc[BBS];
__device__ int   g_hist[BBS * 64];
__device__ float g_psum[BBS * 4];

// ---------------- helpers ----------------
__device__ __forceinline__ uint32_t smem_u32(const void* p) {
    uint32_t a;
    asm("{ .reg .u64 t; cvta.to.shared.u64 t, %1; cvt.u32.u64 %0, t; }" : "=r"(a) : "l"(p));
    return a;
}
__device__ __forceinline__ uint32_t pack_bf16(float a, float b) {
    __nv_bfloat162 h = __floats2bfloat162_rn(a, b);
    return *(uint32_t*)&h;
}
__device__ __forceinline__ void ldsm_x4(uint32_t* r, uint32_t addr) {
    asm volatile("ldmatrix.sync.aligned.m8n8.x4.shared.b16 {%0,%1,%2,%3}, [%4];"
        : "=r"(r[0]), "=r"(r[1]), "=r"(r[2]), "=r"(r[3]) : "r"(addr));
}
#define MMA(d, a, b0, b1) \
    asm volatile("mma.sync.aligned.m16n8k16.row.col.f32.bf16.bf16.f32 " \
        "{%0,%1,%2,%3},{%4,%5,%6,%7},{%8,%9},{%0,%1,%2,%3};" \
        : "+f"((d)[0]), "+f"((d)[1]), "+f"((d)[2]), "+f"((d)[3]) \
        : "r"((a)[0]), "r"((a)[1]), "r"((a)[2]), "r"((a)[3]), "r"(b0), "r"(b1))

// smem layout (static, 46208 B < 48 KB)
#define SAS 72                   // A/B row stride in bf16 elems (144 B)
#define OAH 0
#define OAL 18432                // 128*144
#define OBH 36864
#define OBL 41472                // +32*144
#define OTM 46080

// ---------------- K1: mma.sync bf16-split GEMM + softcap + temperature ----------------
__global__ __launch_bounds__(256)
void k1_gemm(const float* __restrict__ emb, const float* __restrict__ hid,
             const int* __restrict__ posp, const float* __restrict__ temps,
             float* __restrict__ outL)
{
    __shared__ __align__(16) char smem[46208];
    const uint32_t sb = smem_u32(smem);
    const int t = threadIdx.x, wid = t >> 5, l = t & 31;
    const int v0 = blockIdx.x * VT;
    const int pos = posp[0];

    if (t < 32) *(float*)(smem + OTM + t * 4) = temps[t];

    // accumulators: 4 n-tiles x 4 f32
    float d[4][4];
    #pragma unroll
    for (int i = 0; i < 4; i++)
        #pragma unroll
        for (int j = 0; j < 4; j++) d[i][j] = 0.f;

    // ldmatrix lane address geometry
    const int m0 = wid * 16;
    const int arow = (l < 16) ? l : l - 16;
    const int acol = (l < 16) ? 0 : 8;
    const uint32_t aoff = ((m0 + arow) * SAS + acol) * 2;
    const int brow = (l & 7) + ((l >= 16) ? 8 : 0);
    const int bcol = (l & 8) ? 8 : 0;
    const uint32_t boff0 = (brow * SAS + bcol) * 2;
    const uint32_t boff1 = boff0 + 16 * SAS * 2;

    float4 evA[8], evB[2];
    // initial global load (chunk 0), coalesced float4
    #pragma unroll
    for (int i = 0; i < 8; i++) {
        int g = i * 256 + t, row = g >> 4, c4 = g & 15;
        evA[i] = *(const float4*)(emb + (size_t)(v0 + row) * HH + c4 * 4);
    }
    #pragma unroll
    for (int i = 0; i < 2; i++) {
        int g = i * 256 + t, row = g >> 4, c4 = g & 15;
        evB[i] = *(const float4*)(hid + ((size_t)row * SSQ + pos) * HH + c4 * 4);
    }

    for (int c = 0; c < NCH; c++) {
        __syncthreads();   // previous chunk's compute (smem reads) done
        // stage A hi/lo
        #pragma unroll
        for (int i = 0; i < 8; i++) {
            int g = i * 256 + t, row = g >> 4, c4 = g & 15;
            float4 v = evA[i];
            float hx = __bfloat162float(__float2bfloat16(v.x));
            float hy = __bfloat162float(__float2bfloat16(v.y));
            float hz = __bfloat162float(__float2bfloat16(v.z));
            float hw = __bfloat162float(__float2bfloat16(v.w));
            uint32_t off = row * (SAS * 2) + c4 * 8;
            *(uint2*)(smem + OAH + off) = make_uint2(pack_bf16(v.x, v.y), pack_bf16(v.z, v.w));
            *(uint2*)(smem + OAL + off) = make_uint2(pack_bf16(v.x - hx, v.y - hy), pack_bf16(v.z - hz, v.w - hw));
        }
        // stage B hi/lo
        #pragma unroll
        for (int i = 0; i < 2; i++) {
            int g = i * 256 + t, row = g >> 4, c4 = g & 15;
            float4 v = evB[i];
            float hx = __bfloat162float(__float2bfloat16(v.x));
            float hy = __bfloat162float(__float2bfloat16(v.y));
            float hz = __bfloat162float(__float2bfloat16(v.z));
            float hw = __bfloat162float(__float2bfloat16(v.w));
            uint32_t off = row * (SAS * 2) + c4 * 8;
            *(uint2*)(smem + OBH + off) = make_uint2(pack_bf16(v.x, v.y), pack_bf16(v.z, v.w));
            *(uint2*)(smem + OBL + off) = make_uint2(pack_bf16(v.x - hx, v.y - hy), pack_bf16(v.z - hz, v.w - hw));
        }
        __syncthreads();
        // prefetch next chunk
        int kn = (c + 1) * KCH;
        if (kn < HH) {
            #pragma unroll
            for (int i = 0; i < 8; i++) {
                int g = i * 256 + t, row = g >> 4, c4 = g & 15;
                evA[i] = *(const float4*)(emb + (size_t)(v0 + row) * HH + kn + c4 * 4);
            }
            #pragma unroll
            for (int i = 0; i < 2; i++) {
                int g = i * 256 + t, row = g >> 4, c4 = g & 15;
                evB[i] = *(const float4*)(hid + ((size_t)row * SSQ + pos) * HH + kn + c4 * 4);
            }
        }
        // compute: 4 k16-steps, 3-term bf16 split
        #pragma unroll
        for (int ks = 0; ks < 4; ks++) {
            uint32_t ko = ks * 32;   // 16 elems * 2 B
            uint32_t aH[4], aL[4], bH0[4], bH1[4], bL0[4], bL1[4];
            ldsm_x4(aH,  sb + OAH + aoff  + ko);
            ldsm_x4(aL,  sb + OAL + aoff  + ko);
            ldsm_x4(bH0, sb + OBH + boff0 + ko);
            ldsm_x4(bH1, sb + OBH + boff1 + ko);
            ldsm_x4(bL0, sb + OBL + boff0 + ko);
            ldsm_x4(bL1, sb + OBL + boff1 + ko);
            MMA(d[0], aH, bH0[0], bH0[1]);
            MMA(d[1], aH, bH0[2], bH0[3]);
            MMA(d[2], aH, bH1[0], bH1[1]);
            MMA(d[3], aH, bH1[2], bH1[3]);
            MMA(d[0], aH, bL0[0], bL0[1]);
            MMA(d[1], aH, bL0[2], bL0[3]);
            MMA(d[2], aH, bL1[0], bL1[1]);
            MMA(d[3], aH, bL1[2], bL1[3]);
            MMA(d[0], aL, bH0[0], bH0[1]);
            MMA(d[1], aL, bH0[2], bH0[3]);
            MMA(d[2], aL, bH1[0], bH1[1]);
            MMA(d[3], aL, bH1[2], bH1[3]);
        }
    }

    // epilogue: softcap + temperature
    const int g = l >> 2, tg = l & 3;
    #pragma unroll
    for (int nt = 0; nt < 4; nt++) {
        int b0 = nt * 8 + tg * 2;
        float t0 = *(float*)(smem + OTM + b0 * 4);
        float t1 = *(float*)(smem + OTM + (b0 + 1) * 4);
        int vlo = v0 + m0 + g, vhi = vlo + 8;
        outL[(size_t)b0 * VV + vlo]       = tanhf(d[nt][0] / 30.0f) * 30.0f / t0;
        outL[(size_t)(b0 + 1) * VV + vlo] = tanhf(d[nt][1] / 30.0f) * 30.0f / t1;
        outL[(size_t)b0 * VV + vhi]       = tanhf(d[nt][2] / 30.0f) * 30.0f / t0;
        outL[(size_t)(b0 + 1) * VV + vhi] = tanhf(d[nt][3] / 30.0f) * 30.0f / t1;
    }
}

// ---------------- monotonic float<->uint ----------------
__device__ __forceinline__ unsigned int enc_f(float f) {
    unsigned int u = __float_as_uint(f);
    return (u & 0x80000000u) ? ~u : (u | 0x80000000u);
}
__device__ __forceinline__ float dec_f(unsigned int e) {
    unsigned int u = (e & 0x80000000u) ? (e & 0x7fffffffu) : ~e;
    return __uint_as_float(u);
}

// ---------------- k0: init scratch ----------------
__global__ void k0_init() {
    int t = threadIdx.x;
    if (t < BBS) { g_max_enc[t] = 0u; g_cand_cnt[t] = 0; }
    for (int i = t; i < BBS * 64; i += 256) g_hist[i] = 0;
}

// ---------------- k2a: per-row max (4 slices/row) ----------------
__global__ void k2a_max(const float* __restrict__ outL) {
    int b = blockIdx.y, sl = blockIdx.x, t = threadIdx.x;
    int wid = t >> 5, lane = t & 31;
    __shared__ float sred[8];
    const float4* r4 = (const float4*)(outL + (size_t)b * VV);
    float mx = __int_as_float(0xff800000);
    for (int i = sl * 8000 + t; i < (sl + 1) * 8000; i += 256) {
        float4 v = r4[i];
        mx = fmaxf(mx, fmaxf(fmaxf(v.x, v.y), fmaxf(v.z, v.w)));
    }
    for (int o = 16; o; o >>= 1) mx = fmaxf(mx, __shfl_xor_sync(0xffffffffu, mx, o));
    if (lane == 0) sred[wid] = mx;
    __syncthreads();
    if (t == 0) {
        float m = sred[0];
        for (int i = 1; i < 8; i++) m = fmaxf(m, sred[i]);
        atomicMax(&g_max_enc[b], enc_f(m));
    }
}

// ---------------- k2b: sum(exp) partials + histogram ----------------
__global__ void k2b_sum(const float* __restrict__ outL) {
    int b = blockIdx.y, sl = blockIdx.x, t = threadIdx.x;
    int wid = t >> 5, lane = t & 31;
    __shared__ int wh[8 * 64];
    __shared__ float sred[8];
    for (int i = t; i < 8 * 64; i += 256) wh[i] = 0;
    __syncthreads();
    const float mx = dec_f(g_max_enc[b]);
    const float4* r4 = (const float4*)(outL + (size_t)b * VV);
    float sum = 0.f;
    for (int i = sl * 8000 + t; i < (sl + 1) * 8000; i += 256) {
        float4 v = r4[i];
        sum += expf(v.x - mx) + expf(v.y - mx) + expf(v.z - mx) + expf(v.w - mx);
        atomicAdd(&wh[wid * 64 + min(63, (int)((mx - v.x) * 2.0f))], 1);
        atomicAdd(&wh[wid * 64 + min(63, (int)((mx - v.y) * 2.0f))], 1);
        atomicAdd(&wh[wid * 64 + min(63, (int)((mx - v.z) * 2.0f))], 1);
        atomicAdd(&wh[wid * 64 + min(63, (int)((mx - v.w) * 2.0f))], 1);
    }
    for (int o = 16; o; o >>= 1) sum += __shfl_xor_sync(0xffffffffu, sum, o);
    if (lane == 0) sred[wid] = sum;
    __syncthreads();
    if (t == 0) {
        float s = 0.f;
        for (int i = 0; i < 8; i++) s += sred[i];   // deterministic order
        g_psum[b * 4 + sl] = s;
    }
    if (t < 64) {
        int c = 0;
        for (int w = 0; w < 8; w++) c += wh[w * 64 + t];
        atomicAdd(&g_hist[b * 64 + t], c);
    }
}

// ---------------- k2c: threshold + candidate collection ----------------
__global__ void k2c_collect(const float* __restrict__ outL) {
    int b = blockIdx.y, sl = blockIdx.x, t = threadIdx.x;
    __shared__ int s_bs;
    __shared__ float s_mx;
    if (t == 0) {
        float mx = dec_f(g_max_enc[b]);
        float S = g_psum[b * 4] + g_psum[b * 4 + 1] + g_psum[b * 4 + 2] + g_psum[b * 4 + 3];
        int cum = 0, bs = 63;
        for (int i = 0; i < 64; i++) { cum += g_hist[b * 64 + i]; if (cum >= 64) { bs = i; break; } }
        s_bs = bs; s_mx = mx;
        if (sl == 0) { g_row_max[b] = mx; g_row_sum[b] = S; }
    }
    __syncthreads();
    const float mx = s_mx;
    const int bs = s_bs;
    const float4* r4 = (const float4*)(outL + (size_t)b * VV);
    for (int i = sl * 8000 + t; i < (sl + 1) * 8000; i += 256) {
        float4 v = r4[i];
        float vals[4] = {v.x, v.y, v.z, v.w};
        #pragma unroll
        for (int j = 0; j < 4; j++) {
            int bin = min(63, (int)((mx - vals[j]) * 2.0f));
            if (bin <= bs) {
                int p = atomicAdd(&g_cand_cnt[b], 1);
                if (p < CAP) { g_cand_val[b * CAP + p] = vals[j]; g_cand_idx[b * CAP + p] = i * 4 + j; }
            }
        }
    }
}

// ---------------- Threefry-2x32 (JAX partitionable, key(42)) ----------------
__device__ __forceinline__ void tf_round(uint32_t &x0, uint32_t &x1, int r) {
    x0 += x1; x1 = (x1 << r) | (x1 >> (32 - r)); x1 ^= x0;
}
__device__ float gumbel_for(uint32_t n) {
    uint32_t x0 = 0u, x1 = n;
    const uint32_t k0 = 0u, k1 = 42u, k2 = 0x1BD11BDAu ^ k0 ^ k1;
    x0 += k0; x1 += k1;
    tf_round(x0,x1,13); tf_round(x0,x1,15); tf_round(x0,x1,26); tf_round(x0,x1,6);
    x0 += k1; x1 += k2 + 1u;
    tf_round(x0,x1,17); tf_round(x0,x1,29); tf_round(x0,x1,16); tf_round(x0,x1,24);
    x0 += k2; x1 += k0 + 2u;
    tf_round(x0,x1,13); tf_round(x0,x1,15); tf_round(x0,x1,26); tf_round(x0,x1,6);
    x0 += k0; x1 += k1 + 3u;
    tf_round(x0,x1,17); tf_round(x0,x1,29); tf_round(x0,x1,16); tf_round(x0,x1,24);
    x0 += k1; x1 += k2 + 4u;
    tf_round(x0,x1,13); tf_round(x0,x1,15); tf_round(x0,x1,26); tf_round(x0,x1,6);
    x0 += k2; x1 += k0 + 5u;
    uint32_t bits = x0 ^ x1;
    float u = __uint_as_float((bits >> 9) | 0x3f800000u) - 1.0f;
    u = u + 1.17549435e-38f;
    u = fmaxf(1.17549435e-38f, u);
    return -logf(-logf(u));
}

// ---------------- K3: exact rank, top-p/top-k, gumbel argmax ----------------
__global__ void k3_sample(const float* __restrict__ tps, const int* __restrict__ tks,
                          float* __restrict__ out)
{
    const int b = blockIdx.x, tid = threadIdx.x;
    __shared__ float sv[CAP];
    __shared__ int   si[CAP];
    __shared__ float tv[64];
    __shared__ int   tix[64];

    int n = g_cand_cnt[b]; if (n > CAP) n = CAP;
    for (int i = tid; i < n; i += 256) { sv[i] = g_cand_val[b * CAP + i]; si[i] = g_cand_idx[b * CAP + i]; }
    __syncthreads();

    for (int j = tid; j < n; j += 256) {
        float v = sv[j]; int id = si[j]; int r = 0;
        for (int i = 0; i < n; i++) {
            float vi = sv[i];
            if (vi > v || (vi == v && si[i] < id)) r++;
        }
        if (r < 64) { tv[r] = v; tix[r] = id; }
    }
    __syncthreads();

    if (tid == 0) {
        int m = n < 64 ? n : 64;
        float mx = g_row_max[b], S = g_row_sum[b];
        float tp = tps[b]; int kk = tks[b];
        float cum = 0.f, best = __int_as_float(0xff800000);
        int bid = 0;
        for (int j = 0; j < m; j++) {
            float p = expf(tv[j] - mx) / S;
            cum += p;
            bool keep = !((cum - p) > tp) && (j < kk);
            if (keep) {
                float sc = tv[j] + gumbel_for((uint32_t)(b * VV + tix[j]));
                if (sc > best) { best = sc; bid = tix[j]; }
            }
        }
        out[b] = (float)bid;
    }
}

// ---------------- launch ----------------
extern "C" void kernel_launch(void* const* d_in, const int* in_sizes, int n_in,
                              void* d_out, int out_size)
{
    const float* emb  = (const float*)d_in[0];
    const float* hid  = (const float*)d_in[1];
    const int*   posp = (const int*)  d_in[2];
    const float* tps  = (const float*)d_in[3];
    const int*   tks  = (const int*)  d_in[4];
    const float* tmps = (const float*)d_in[5];
    float* out  = (float*)d_out;
    float* outL = out + BBS;

    k0_init<<<1, 256>>>();
    k1_gemm<<<VV / VT, 256>>>(emb, hid, posp, tmps, outL);
    dim3 g4(4, BBS);
    k2a_max<<<g4, 256>>>(outL);
    k2b_sum<<<g4, 256>>>(outL);
    k2c_collect<<<g4, 256>>>(outL);
    k3_sample<<<BBS, 256>>>(tps, tks, out);
}